// round 1
// baseline (speedup 1.0000x reference)
#include <cuda_runtime.h>
#include <cstdint>
#include <cstddef>

#define Bn 256
#define Ln 1024
#define Vn 40
#define Hn 128

// 134 MB scratch for the hidden-state sequence [B, L, H] (alloc-free rule).
__device__ float g_hseq[(size_t)Bn * Ln * Hn];

// ---- packed f32x2 helpers (FFMA2 only reachable via PTX) ----
__device__ __forceinline__ unsigned long long ffma2(unsigned long long a,
                                                    unsigned long long b,
                                                    unsigned long long c) {
    unsigned long long d;
    asm("fma.rn.f32x2 %0, %1, %2, %3;" : "=l"(d) : "l"(a), "l"(b), "l"(c));
    return d;
}
__device__ __forceinline__ unsigned long long add2(unsigned long long a,
                                                   unsigned long long b) {
    unsigned long long d;
    asm("add.rn.f32x2 %0, %1, %2;" : "=l"(d) : "l"(a), "l"(b));
    return d;
}
__device__ __forceinline__ float plo(unsigned long long a) {
    return __int_as_float((int)(unsigned)(a & 0xffffffffull));
}
__device__ __forceinline__ float phi(unsigned long long a) {
    return __int_as_float((int)(unsigned)(a >> 32));
}
__device__ __forceinline__ float tanh_fast(float x) {
    float r;
    asm("tanh.approx.f32 %0, %1;" : "=f"(r) : "f"(x));
    return r;
}

// =====================================================================
// Phase 1: per-batch-row recurrence. One CTA per batch element,
// 128 threads; thread t owns row t of Wh in registers (64 packed f32x2).
// h ping-pongs in shared memory; embedding + x row cached in shared.
// =====================================================================
__global__ void __launch_bounds__(Hn) rnn_scan_kernel(
    const int* __restrict__ x, const float* __restrict__ h0,
    const float* __restrict__ emb, const float* __restrict__ Wh,
    const float* __restrict__ bh, float* __restrict__ final_h)
{
    __shared__ __align__(16) float s_emb[Vn * Hn];   // 20 KB
    __shared__ int s_x[Ln];                          // 4 KB
    __shared__ __align__(16) float s_h[2][Hn];       // ping-pong h

    const int t = threadIdx.x;
    const int b = blockIdx.x;

    for (int i = t; i < Vn * Hn; i += Hn) s_emb[i] = emb[i];
    for (int i = t; i < Ln; i += Hn) s_x[i] = x[b * Ln + i];
    s_h[0][t] = h0[b * Hn + t];
    const float bh_t = bh[t];

    // Wh row t -> 64 packed pairs (Wh[t][2k], Wh[t][2k+1]) in registers
    unsigned long long wh[Hn / 2];
    const unsigned long long* wp = (const unsigned long long*)(Wh + t * Hn);
#pragma unroll
    for (int i = 0; i < Hn / 2; i++) wh[i] = wp[i];

    __syncthreads();

    float hn = s_h[0][t];
    float* orow = g_hseq + (size_t)b * Ln * Hn + t;

#pragma unroll 1
    for (int l = 0; l < Ln; l++) {
        const int idx = s_x[l];
        const float e = s_emb[idx * Hn + t];

        const ulonglong2* hp = (const ulonglong2*)s_h[l & 1];
        unsigned long long a0 = 0, a1 = 0, a2 = 0, a3 = 0;
#pragma unroll
        for (int k = 0; k < Hn / 4; k += 2) {
            ulonglong2 p = hp[k];        // LDS.128, broadcast
            a0 = ffma2(wh[2 * k + 0], p.x, a0);
            a1 = ffma2(wh[2 * k + 1], p.y, a1);
            ulonglong2 q = hp[k + 1];
            a2 = ffma2(wh[2 * k + 2], q.x, a2);
            a3 = ffma2(wh[2 * k + 3], q.y, a3);
        }
        a0 = add2(a0, a2);
        a1 = add2(a1, a3);
        a0 = add2(a0, a1);

        const float s = plo(a0) + phi(a0) + e + bh_t;
        hn = tanh_fast(s);

        s_h[(l + 1) & 1][t] = hn;       // write next buffer (no race: double-buffered)
        orow[(size_t)l * Hn] = hn;      // coalesced 512B/step store
        __syncthreads();
    }

    final_h[b * Hn + t] = hn;
}

// =====================================================================
// Phase 2: logits[r, v] = sum_k hseq[r, k] * Wo[v, k] + b_y[v]
// 256 threads/block, one row per thread, Wo resident in shared,
// f32x2-packed over k. 1024 blocks cover all 262144 rows.
// =====================================================================
__global__ void __launch_bounds__(256) logits_kernel(
    const float* __restrict__ Wo, const float* __restrict__ by,
    float* __restrict__ out)
{
    __shared__ __align__(16) float s_wo[Vn * Hn];    // 20 KB
    const int tid = threadIdx.x;
    for (int i = tid; i < Vn * Hn; i += 256) s_wo[i] = Wo[i];
    __syncthreads();

    const size_t r = (size_t)blockIdx.x * 256 + tid;
    const ulonglong2* h2 = (const ulonglong2*)(g_hseq + r * Hn);

    unsigned long long acc[Vn];
#pragma unroll
    for (int v = 0; v < Vn; v++) acc[v] = 0;

#pragma unroll 1
    for (int c = 0; c < 8; c++) {               // 8 chunks of 16 floats
        unsigned long long hh[8];
#pragma unroll
        for (int i = 0; i < 4; i++) {           // 4x LDG.128
            ulonglong2 p = h2[c * 4 + i];
            hh[2 * i] = p.x;
            hh[2 * i + 1] = p.y;
        }
        const unsigned long long* wbase = (const unsigned long long*)s_wo + c * 8;
#pragma unroll
        for (int v = 0; v < Vn; v++) {
            const unsigned long long* w = wbase + (size_t)v * (Hn / 2);
            unsigned long long a = acc[v];
#pragma unroll
            for (int i = 0; i < 8; i++) a = ffma2(hh[i], w[i], a);
            acc[v] = a;
        }
    }

    float4* o4 = (float4*)(out + r * Vn);       // 160B per row, 16B aligned
#pragma unroll
    for (int j = 0; j < Vn / 4; j++) {
        float4 o;
        o.x = plo(acc[4 * j + 0]) + phi(acc[4 * j + 0]) + by[4 * j + 0];
        o.y = plo(acc[4 * j + 1]) + phi(acc[4 * j + 1]) + by[4 * j + 1];
        o.z = plo(acc[4 * j + 2]) + phi(acc[4 * j + 2]) + by[4 * j + 2];
        o.w = plo(acc[4 * j + 3]) + phi(acc[4 * j + 3]) + by[4 * j + 3];
        o4[j] = o;
    }
}

extern "C" void kernel_launch(void* const* d_in, const int* in_sizes, int n_in,
                              void* d_out, int out_size)
{
    const int*   x   = (const int*)d_in[0];
    const float* h0  = (const float*)d_in[1];
    const float* emb = (const float*)d_in[2];
    const float* Wh  = (const float*)d_in[3];
    const float* Wo  = (const float*)d_in[4];
    const float* bh  = (const float*)d_in[5];
    const float* by  = (const float*)d_in[6];

    float* out     = (float*)d_out;
    float* logits  = out;                               // [B, L, V]
    float* final_h = out + (size_t)Bn * Ln * Vn;        // [B, H]

    rnn_scan_kernel<<<Bn, Hn>>>(x, h0, emb, Wh, bh, final_h);
    logits_kernel<<<(Bn * Ln) / 256, 256>>>(Wo, by, logits);
}